// round 12
// baseline (speedup 1.0000x reference)
#include <cuda_runtime.h>

#define DIM 4096
#define NQ 12
#define DEPTH 4

// sigma^{-1} of the CNOT ring (store-side fusion), GF(2)-linear, verified R9-R11.
__host__ __device__ __forceinline__ constexpr int sig_inv(int x) {
    int y = 0, suf = 0;
    for (int i = 11; i >= 1; --i) {
        suf ^= (x >> i) & 1;
        if (i <= 10) y |= suf << i;
    }
    const int all = suf ^ (x & 1);
    y |= all;
    y |= (all ^ ((x >> 11) & 1)) << 11;
    return y;
}
// Placement for both buffers (512-thread layouts): fold bit5->bit2, (bit8^bit6)->bit4.
// Preserves bits 0-1 (float4 chunks intact). Verified full-rank for:
//  * A vec chunks (lane at bits 3-7): per-8-lane phase bank-group (c^l2, l0, l1^wid0[^1]) injective
//  * B scalar load (lane at bits 0-3,8): banks (l0,l1,l2^c,l3,l4^c) injective
//  * B scatter via sig_inv: basis bank rows {00001,00011,00111,01111,11011} rank-5
__host__ __device__ __forceinline__ constexpr int PH2(int j) {
    return j ^ (((j >> 5) & 1) << 2) ^ ((((j >> 8) ^ (j >> 6)) & 1) << 4);
}
// PH2(sig_inv(k<<9)) basis images (hand-computed):
//  e9 -> sig_inv=0xBFF -> PH2=0xBFB ; e10 -> 0xFFF -> 0xFFB ; e11 -> 0x7FF -> 0x7FB
__host__ __device__ __forceinline__ constexpr int KC2(int k) {
    return ((k & 1) ? 0xBFB : 0) ^ ((k & 2) ? 0xFFB : 0) ^ ((k & 4) ? 0x7FB : 0);
}

__global__ __launch_bounds__(512, 1)
void qsim_kernel(const float* __restrict__ x, const float* __restrict__ theta,
                 const float* __restrict__ w, const float* __restrict__ b,
                 float* __restrict__ out) {
    __shared__ __align__(16) float S0[DIM];   // inter-layer buffer (PH2 placement)
    __shared__ __align__(16) float S1[DIM];   // intra-layer buffer (PH2 placement)
    __shared__ float CS[DEPTH * NQ];
    __shared__ float SN[DEPTH * NQ];
    __shared__ float red[32];

    const int tid = threadIdx.x;
    const int lane = tid & 31;
    const int wid = tid >> 5;   // 0..15

    // half-angle tables
    if (tid < DEPTH * NQ) {
        const int q = tid % NQ;
        float s, c;
        __sincosf(0.5f * (theta[tid] + 0.1f * x[q]), &s, &c);
        CS[tid] = c;
        SN[tid] = s;
    }
    __syncthreads();

    // Layout A: j = wid<<8 | lane<<3 | k    (k bits 0-2 = qubits 11..9,
    //            lane bits 3-7 = qubits 8..4, wid bits 8-11)
    // Layout B: i = k<<9 | (lane>>4)<<8 | wid<<4 | (lane&15)
    //            (lane_lo bits 0-3, wid bits 4-7, lane bit4 at bit 8 = qubit 3,
    //             k bits 9-11 = qubits 2..0)
    const int baseA = (wid << 8) | (lane << 3);
    const int baseB = ((lane >> 4) << 8) | (wid << 4) | (lane & 15);

    const int aAddr0 = PH2(baseA);          // A chunk 0 (k=0..3)
    const int aAddr1 = PH2(baseA | 4);      // A chunk 1 (k=4..7)
    const int bAddr = PH2(baseB);           // B-load base; +512k (PH2 ignores bits 9-11)
    const int sb = PH2(sig_inv(baseB));     // B-store base; ^KC2(k) compile-time

    float v[8];

    // ============ Layer 0: product state (12 RYs on e0), ring-0 fused in store ====
    {
        float P = 1.f;
#pragma unroll
        for (int bp = 0; bp < 9; ++bp)             // i bit bp -> qubit 11-bp
            P *= ((baseB >> bp) & 1) ? SN[11 - bp] : CS[11 - bp];
#pragma unroll
        for (int k = 0; k < 8; ++k) {
            const float a = P * ((k & 1) ? SN[2] : CS[2])
                              * ((k & 2) ? SN[1] : CS[1])
                              * ((k & 4) ? SN[0] : CS[0]);
            S0[sb ^ KC2(k)] = a;
        }
    }
    __syncthreads();

    // ============ Layers 1..3 — rolled to keep code size inside I$ ============
#pragma unroll 1
    for (int d = 1; d < DEPTH; ++d) {
        const float* C = CS + d * NQ;
        const float* Sn = SN + d * NQ;

        // ---- Pass A: float4 gather (plain; prev ring was store-fused),
        //      rotate qubits 11..9 (k bits, in-reg) + 8..4 (lane shfl),
        //      float4 scatter to S1.
        {
            const float4 p0 = *reinterpret_cast<const float4*>(&S0[aAddr0]);
            const float4 p1 = *reinterpret_cast<const float4*>(&S0[aAddr1]);
            v[0] = p0.x; v[1] = p0.y; v[2] = p0.z; v[3] = p0.w;
            v[4] = p1.x; v[5] = p1.y; v[6] = p1.z; v[7] = p1.w;
        }
#pragma unroll
        for (int rb = 0; rb < 3; ++rb) {           // k bit rb -> qubit 11-rb
            const int m = 1 << rb;
            const float c = C[11 - rb], s = Sn[11 - rb];
#pragma unroll
            for (int k = 0; k < 8; ++k)
                if (!(k & m)) {
                    const float lo = v[k], hi = v[k | m];
                    v[k]     = fmaf(c, lo, -s * hi);
                    v[k | m] = fmaf(s, lo,  c * hi);
                }
        }
#pragma unroll
        for (int bs = 0; bs < 5; ++bs) {           // lane bit bs -> qubit 8-bs
            const int m = 1 << bs;
            const float c = C[8 - bs], s = Sn[8 - bs];
            const float se = (lane & m) ? s : -s;
#pragma unroll
            for (int k = 0; k < 8; ++k) {
                const float o = __shfl_xor_sync(0xffffffffu, v[k], m);
                v[k] = fmaf(c, v[k], se * o);
            }
        }
        *reinterpret_cast<float4*>(&S1[aAddr0]) = make_float4(v[0], v[1], v[2], v[3]);
        *reinterpret_cast<float4*>(&S1[aAddr1]) = make_float4(v[4], v[5], v[6], v[7]);
        __syncthreads();

        // ---- Pass B: scalar gather (immediate +512k), rotate qubit 3 (shfl on
        //      lane bit 4) + qubits 2..0 (k bits, in-reg), scatter with ring-d
        //      fused (constant XORs).
#pragma unroll
        for (int k = 0; k < 8; ++k) v[k] = S1[bAddr + (k << 9)];

        {
            const float c = C[3], s = Sn[3];
            const float se = (lane & 16) ? s : -s;
#pragma unroll
            for (int k = 0; k < 8; ++k) {
                const float o = __shfl_xor_sync(0xffffffffu, v[k], 16);
                v[k] = fmaf(c, v[k], se * o);
            }
        }
#pragma unroll
        for (int rb = 0; rb < 3; ++rb) {           // k bit rb -> i bit 9+rb -> qubit 2-rb
            const int m = 1 << rb;
            const float c = C[2 - rb], s = Sn[2 - rb];
#pragma unroll
            for (int k = 0; k < 8; ++k)
                if (!(k & m)) {
                    const float lo = v[k], hi = v[k | m];
                    v[k]     = fmaf(c, lo, -s * hi);
                    v[k | m] = fmaf(s, lo,  c * hi);
                }
        }
#pragma unroll
        for (int k = 0; k < 8; ++k) S0[sb ^ KC2(k)] = v[k];
        __syncthreads();
    }

    // ============ Readout: float4 gather (final ring already fused) ========
    {
        const float4 p0 = *reinterpret_cast<const float4*>(&S0[aAddr0]);
        const float4 p1 = *reinterpret_cast<const float4*>(&S0[aAddr1]);
        v[0] = p0.x; v[1] = p0.y; v[2] = p0.z; v[3] = p0.w;
        v[4] = p1.x; v[5] = p1.y; v[6] = p1.z; v[7] = p1.w;
    }
#pragma unroll
    for (int m2 = 0; m2 < 4; ++m2)   // state out: 8B-aligned pairs
        *reinterpret_cast<float2*>(out + 2 + baseA + 2 * m2) =
            make_float2(v[2 * m2], v[2 * m2 + 1]);
    float a0, a1;
    {
        const float4 w00 = *reinterpret_cast<const float4*>(w + baseA);
        const float4 w01 = *reinterpret_cast<const float4*>(w + baseA + 4);
        const float4 w10 = *reinterpret_cast<const float4*>(w + DIM + baseA);
        const float4 w11 = *reinterpret_cast<const float4*>(w + DIM + baseA + 4);
        const float p0 = v[0] * v[0], p1 = v[1] * v[1], p2 = v[2] * v[2], p3 = v[3] * v[3];
        const float p4 = v[4] * v[4], p5 = v[5] * v[5], p6 = v[6] * v[6], p7 = v[7] * v[7];
        a0 = p0 * w00.x + p1 * w00.y + p2 * w00.z + p3 * w00.w
           + p4 * w01.x + p5 * w01.y + p6 * w01.z + p7 * w01.w;
        a1 = p0 * w10.x + p1 * w10.y + p2 * w10.z + p3 * w10.w
           + p4 * w11.x + p5 * w11.y + p6 * w11.z + p7 * w11.w;
    }
#pragma unroll
    for (int o = 16; o > 0; o >>= 1) {
        a0 += __shfl_down_sync(0xffffffffu, a0, o);
        a1 += __shfl_down_sync(0xffffffffu, a1, o);
    }
    if (lane == 0) { red[wid] = a0; red[16 + wid] = a1; }
    __syncthreads();
    if (wid == 0) {
        float r0 = (lane < 16) ? red[lane] : 0.f;
        float r1 = (lane < 16) ? red[16 + lane] : 0.f;
#pragma unroll
        for (int o = 8; o > 0; o >>= 1) {
            r0 += __shfl_down_sync(0xffffffffu, r0, o);
            r1 += __shfl_down_sync(0xffffffffu, r1, o);
        }
        if (lane == 0) {
            out[0] = r0 + b[0];
            out[1] = r1 + b[1];
        }
    }
}

extern "C" void kernel_launch(void* const* d_in, const int* in_sizes, int n_in,
                              void* d_out, int out_size) {
    const float* x = nullptr;
    const float* th = nullptr;
    const float* w = nullptr;
    const float* b = nullptr;
    for (int i = 0; i < n_in; ++i) {
        const int s = in_sizes[i];
        if (s == NQ) x = (const float*)d_in[i];
        else if (s == DEPTH * NQ) th = (const float*)d_in[i];
        else if (s == 2 * DIM) w = (const float*)d_in[i];
        else if (s == 2) b = (const float*)d_in[i];
    }
    qsim_kernel<<<1, 512>>>(x, th, w, b, (float*)d_out);
}

// round 13
// speedup vs baseline: 1.0952x; 1.0952x over previous
#include <cuda_runtime.h>

#define DIM 4096
#define NQ 12
#define DEPTH 4

// sigma^{-1} of the CNOT ring (store-side fusion), GF(2)-linear, verified R9-R12.
__host__ __device__ __forceinline__ constexpr int sig_inv(int x) {
    int y = 0, suf = 0;
    for (int i = 11; i >= 1; --i) {
        suf ^= (x >> i) & 1;
        if (i <= 10) y |= suf << i;
    }
    const int all = suf ^ (x & 1);
    y |= all;
    y |= (all ^ ((x >> 11) & 1)) << 11;
    return y;
}
// Placement (both buffers), verified conflict-free in R12 (passed):
// fold bit5->bit2, (bit8^bit6)->bit4; preserves bits 0-1 (float4 legal).
__host__ __device__ __forceinline__ constexpr int PH2(int j) {
    return j ^ (((j >> 5) & 1) << 2) ^ ((((j >> 8) ^ (j >> 6)) & 1) << 4);
}
// PH2(sig_inv(k<<9)) basis images (verified R12, kernel passed):
__host__ __device__ __forceinline__ constexpr int KC2(int k) {
    return ((k & 1) ? 0xBFB : 0) ^ ((k & 2) ? 0xFFB : 0) ^ ((k & 4) ? 0x7FB : 0);
}

__global__ __launch_bounds__(512, 1)
void qsim_kernel(const float* __restrict__ x, const float* __restrict__ theta,
                 const float* __restrict__ w, const float* __restrict__ b,
                 float* __restrict__ out) {
    __shared__ __align__(16) float S0[DIM];   // inter-layer buffer (PH2 placement)
    __shared__ __align__(16) float S1[DIM];   // intra-layer buffer (PH2 placement)
    __shared__ float CS[DEPTH * NQ];   // cos
    __shared__ float SN[DEPTH * NQ];   // sin
    __shared__ float TN[DEPTH * NQ];   // tan(a/2) = s/(1+c)  (lifting shear)
    __shared__ float red[32];

    const int tid = threadIdx.x;
    const int lane = tid & 31;
    const int wid = tid >> 5;   // 0..15

    // Layout A: j = wid<<8 | lane<<3 | k    (k bits 0-2 = qubits 11..9,
    //            lane bits 3-7 = qubits 8..4, wid bits 8-11)
    const int baseA = (wid << 8) | (lane << 3);

    // -------- prefetch w into registers NOW; consumed in the tail (hides L2/DRAM) --
    float4 w00, w01, w10, w11;
    {
        w00 = *reinterpret_cast<const float4*>(w + baseA);
        w01 = *reinterpret_cast<const float4*>(w + baseA + 4);
        w10 = *reinterpret_cast<const float4*>(w + DIM + baseA);
        w11 = *reinterpret_cast<const float4*>(w + DIM + baseA + 4);
    }

    // half-angle tables
    if (tid < DEPTH * NQ) {
        const int q = tid % NQ;
        float s, c;
        __sincosf(0.5f * (theta[tid] + 0.1f * x[q]), &s, &c);
        CS[tid] = c;
        SN[tid] = s;
        TN[tid] = s / (1.f + c);
    }
    __syncthreads();

    // Layout B: i = k<<9 | (lane>>4)<<8 | wid<<4 | (lane&15)
    //            (lane_lo bits 0-3, wid bits 4-7, lane bit4 at bit 8 = qubit 3,
    //             k bits 9-11 = qubits 2..0)
    const int baseB = ((lane >> 4) << 8) | (wid << 4) | (lane & 15);

    const int aAddr0 = PH2(baseA);          // A chunk 0 (k=0..3)
    const int aAddr1 = PH2(baseA | 4);      // A chunk 1 (k=4..7)
    const int bAddr = PH2(baseB);           // B-load base; +512k (PH2 ignores bits 9-11)
    const int sb = PH2(sig_inv(baseB));     // B-store base; ^KC2(k) compile-time

    float v[8];

    // ============ Layer 0: product state (12 RYs on e0), ring-0 fused in store ====
    {
        float P = 1.f;
#pragma unroll
        for (int bp = 0; bp < 9; ++bp)             // i bit bp -> qubit 11-bp
            P *= ((baseB >> bp) & 1) ? SN[11 - bp] : CS[11 - bp];
#pragma unroll
        for (int k = 0; k < 8; ++k) {
            const float a = P * ((k & 1) ? SN[2] : CS[2])
                              * ((k & 2) ? SN[1] : CS[1])
                              * ((k & 4) ? SN[0] : CS[0]);
            S0[sb ^ KC2(k)] = a;
        }
    }
    __syncthreads();

    // ============ Layers 1..3 — rolled to keep code size inside I$ ============
#pragma unroll 1
    for (int d = 1; d < DEPTH; ++d) {
        const float* C = CS + d * NQ;
        const float* Sn = SN + d * NQ;
        const float* Tn = TN + d * NQ;

        // ---- Pass A: float4 gather (plain; prev ring was store-fused),
        //      rotate qubits 11..9 (k bits, lifting) + 8..4 (lane shfl),
        //      float4 scatter to S1.
        {
            const float4 p0 = *reinterpret_cast<const float4*>(&S0[aAddr0]);
            const float4 p1 = *reinterpret_cast<const float4*>(&S0[aAddr1]);
            v[0] = p0.x; v[1] = p0.y; v[2] = p0.z; v[3] = p0.w;
            v[4] = p1.x; v[5] = p1.y; v[6] = p1.z; v[7] = p1.w;
        }
#pragma unroll
        for (int rb = 0; rb < 3; ++rb) {           // k bit rb -> qubit 11-rb
            const int m = 1 << rb;
            const float s = Sn[11 - rb], t = Tn[11 - rb];
#pragma unroll
            for (int k = 0; k < 8; ++k)
                if (!(k & m)) {
                    const float lo = v[k], hi = v[k | m];
                    const float x1 = fmaf(-t, hi, lo);     // lifting: 3 FMA/pair
                    const float y1 = fmaf(s, x1, hi);      //  = s*lo + c*hi
                    v[k]     = fmaf(-t, y1, x1);           //  = c*lo - s*hi
                    v[k | m] = y1;
                }
        }
#pragma unroll
        for (int bs = 0; bs < 5; ++bs) {           // lane bit bs -> qubit 8-bs
            const int m = 1 << bs;
            const float c = C[8 - bs], s = Sn[8 - bs];
            const float se = (lane & m) ? s : -s;
#pragma unroll
            for (int k = 0; k < 8; ++k) {
                const float o = __shfl_xor_sync(0xffffffffu, v[k], m);
                v[k] = fmaf(c, v[k], se * o);
            }
        }
        *reinterpret_cast<float4*>(&S1[aAddr0]) = make_float4(v[0], v[1], v[2], v[3]);
        *reinterpret_cast<float4*>(&S1[aAddr1]) = make_float4(v[4], v[5], v[6], v[7]);
        __syncthreads();

        // ---- Pass B: scalar gather (immediate +512k), rotate qubit 3 (shfl on
        //      lane bit 4) + qubits 2..0 (k bits, lifting), scatter with ring-d
        //      fused (constant XORs).
#pragma unroll
        for (int k = 0; k < 8; ++k) v[k] = S1[bAddr + (k << 9)];

        {
            const float c = C[3], s = Sn[3];
            const float se = (lane & 16) ? s : -s;
#pragma unroll
            for (int k = 0; k < 8; ++k) {
                const float o = __shfl_xor_sync(0xffffffffu, v[k], 16);
                v[k] = fmaf(c, v[k], se * o);
            }
        }
#pragma unroll
        for (int rb = 0; rb < 3; ++rb) {           // k bit rb -> i bit 9+rb -> qubit 2-rb
            const int m = 1 << rb;
            const float s = Sn[2 - rb], t = Tn[2 - rb];
#pragma unroll
            for (int k = 0; k < 8; ++k)
                if (!(k & m)) {
                    const float lo = v[k], hi = v[k | m];
                    const float x1 = fmaf(-t, hi, lo);
                    const float y1 = fmaf(s, x1, hi);
                    v[k]     = fmaf(-t, y1, x1);
                    v[k | m] = y1;
                }
        }
#pragma unroll
        for (int k = 0; k < 8; ++k) S0[sb ^ KC2(k)] = v[k];
        __syncthreads();
    }

    // ============ Readout: float4 gather (final ring already fused) ========
    {
        const float4 p0 = *reinterpret_cast<const float4*>(&S0[aAddr0]);
        const float4 p1 = *reinterpret_cast<const float4*>(&S0[aAddr1]);
        v[0] = p0.x; v[1] = p0.y; v[2] = p0.z; v[3] = p0.w;
        v[4] = p1.x; v[5] = p1.y; v[6] = p1.z; v[7] = p1.w;
    }
#pragma unroll
    for (int m2 = 0; m2 < 4; ++m2)   // state out: 8B-aligned pairs
        *reinterpret_cast<float2*>(out + 2 + baseA + 2 * m2) =
            make_float2(v[2 * m2], v[2 * m2 + 1]);
    float a0, a1;
    {
        const float p0 = v[0] * v[0], p1 = v[1] * v[1], p2 = v[2] * v[2], p3 = v[3] * v[3];
        const float p4 = v[4] * v[4], p5 = v[5] * v[5], p6 = v[6] * v[6], p7 = v[7] * v[7];
        a0 = p0 * w00.x + p1 * w00.y + p2 * w00.z + p3 * w00.w
           + p4 * w01.x + p5 * w01.y + p6 * w01.z + p7 * w01.w;
        a1 = p0 * w10.x + p1 * w10.y + p2 * w10.z + p3 * w10.w
           + p4 * w11.x + p5 * w11.y + p6 * w11.z + p7 * w11.w;
    }
#pragma unroll
    for (int o = 16; o > 0; o >>= 1) {
        a0 += __shfl_down_sync(0xffffffffu, a0, o);
        a1 += __shfl_down_sync(0xffffffffu, a1, o);
    }
    if (lane == 0) { red[wid] = a0; red[16 + wid] = a1; }
    __syncthreads();
    if (wid == 0) {
        float r0 = (lane < 16) ? red[lane] : 0.f;
        float r1 = (lane < 16) ? red[16 + lane] : 0.f;
#pragma unroll
        for (int o = 8; o > 0; o >>= 1) {
            r0 += __shfl_down_sync(0xffffffffu, r0, o);
            r1 += __shfl_down_sync(0xffffffffu, r1, o);
        }
        if (lane == 0) {
            out[0] = r0 + b[0];
            out[1] = r1 + b[1];
        }
    }
}

extern "C" void kernel_launch(void* const* d_in, const int* in_sizes, int n_in,
                              void* d_out, int out_size) {
    const float* x = nullptr;
    const float* th = nullptr;
    const float* w = nullptr;
    const float* b = nullptr;
    for (int i = 0; i < n_in; ++i) {
        const int s = in_sizes[i];
        if (s == NQ) x = (const float*)d_in[i];
        else if (s == DEPTH * NQ) th = (const float*)d_in[i];
        else if (s == 2 * DIM) w = (const float*)d_in[i];
        else if (s == 2) b = (const float*)d_in[i];
    }
    qsim_kernel<<<1, 512>>>(x, th, w, b, (float*)d_out);
}

// round 14
// speedup vs baseline: 1.3480x; 1.2308x over previous
#include <cuda_runtime.h>

#define DIM 4096
#define NQ 12
#define DEPTH 4

// sigma (gather form of the CNOT ring), GF(2)-linear, verified R1-R13.
__host__ __device__ __forceinline__ constexpr int sig(int x) {
    int r = (x ^ (x >> 1)) & 0x3FF;
    r |= (((x >> 10) ^ (x >> 11) ^ x) & 1) << 10;
    r |= (((x >> 11) ^ x) & 1) << 11;
    return r;
}
// sigma^{-1} (store-side fusion), verified R9-R13.
__host__ __device__ __forceinline__ constexpr int sig_inv(int x) {
    int y = 0, suf = 0;
    for (int i = 11; i >= 1; --i) {
        suf ^= (x >> i) & 1;
        if (i <= 10) y |= suf << i;
    }
    const int all = suf ^ (x & 1);
    y |= all;
    y |= (all ^ ((x >> 11) & 1)) << 11;
    return y;
}
// Placement (both buffers), verified conflict-free in R12 (passed).
__host__ __device__ __forceinline__ constexpr int PH2(int j) {
    return j ^ (((j >> 5) & 1) << 2) ^ ((((j >> 8) ^ (j >> 6)) & 1) << 4);
}
// PH2(sig_inv(k<<9)) basis images (verified R12):
__host__ __device__ __forceinline__ constexpr int KC2(int k) {
    return ((k & 1) ? 0xBFB : 0) ^ ((k & 2) ? 0xFFB : 0) ^ ((k & 4) ? 0x7FB : 0);
}
// sig_inv(k<<9) raw basis images (no placement; for global scatter/prefetch):
//  e9 -> 0xBFF ; e10 -> 0xFFF ; e11 -> 0x7FF
__host__ __device__ __forceinline__ constexpr int SI(int k) {
    return ((k & 1) ? 0xBFF : 0) ^ ((k & 2) ? 0xFFF : 0) ^ ((k & 4) ? 0x7FF : 0);
}

__global__ __launch_bounds__(512, 1)
void qsim_kernel(const float* __restrict__ x, const float* __restrict__ theta,
                 const float* __restrict__ w, const float* __restrict__ b,
                 float* __restrict__ out) {
    __shared__ __align__(16) float S0[DIM];   // inter-layer buffer (PH2 placement)
    __shared__ __align__(16) float S1[DIM];   // intra-layer buffer (PH2 placement)
    __shared__ float CS[DEPTH * NQ];
    __shared__ float SN[DEPTH * NQ];
    __shared__ float red[32];

    const int tid = threadIdx.x;
    const int lane = tid & 31;
    const int wid = tid >> 5;   // 0..15

    // Layout A: j = wid<<8 | lane<<3 | k   (k bits 0-2 = qubits 11..9,
    //            lane bits 3-7 = qubits 8..4, wid bits 8-11)
    // Layout B: i = k<<9 | (lane>>4)<<8 | wid<<4 | (lane&15)
    const int baseA = (wid << 8) | (lane << 3);
    const int baseB = ((lane >> 4) << 8) | (wid << 4) | (lane & 15);
    const int sOut = sig_inv(baseB);         // final-state global index base

    // -------- prefetch w at sigma^{-1}-mapped indices (consumed at the very end;
    //          addresses known at entry, latency hidden under ~7us of compute) ----
    float wa[8], wb[8];
#pragma unroll
    for (int k = 0; k < 8; ++k) {
        const int gi = sOut ^ SI(k);
        wa[k] = w[gi];
        wb[k] = w[DIM + gi];
    }

    // half-angle tables
    if (tid < DEPTH * NQ) {
        const int q = tid % NQ;
        float s, c;
        __sincosf(0.5f * (theta[tid] + 0.1f * x[q]), &s, &c);
        CS[tid] = c;
        SN[tid] = s;
    }

    const int aAddr0 = PH2(baseA);           // A chunk 0 (k=0..3)
    const int aAddr1 = PH2(baseA | 4);       // A chunk 1 (k=4..7)
    const int bAddr = PH2(baseB);            // B-load base; +512k
    const int sb = PH2(sig_inv(baseB));      // B-store base; ^KC2(k)

    float v[8];
    __syncthreads();                         // tables ready

    // ============ Layer 1 pass A with layer-0 + ring-0 folded into registers ====
    // postRing0[j] = prod0[sig(j)]; sig linear => u_k = sig(baseA) ^ sig(k).
    {
        const int u0 = sig(baseA);
        float Pfix = 1.f;
#pragma unroll
        for (int bp = 3; bp <= 9; ++bp)      // bits 3..9 -> qubits 8..2 (k-invariant)
            Pfix *= ((u0 >> bp) & 1) ? SN[11 - bp] : CS[11 - bp];
        const float c11 = CS[11], s11 = SN[11], c10 = CS[10], s10 = SN[10];
        const float c9 = CS[9], s9 = SN[9], c1 = CS[1], s1 = SN[1];
        const float c0 = CS[0], s0f = SN[0];
#pragma unroll
        for (int k = 0; k < 8; ++k) {
            const int uk = u0 ^ sig(k);      // sig(k) folds at compile time
            float a = Pfix;
            a *= (uk & 1) ? s11 : c11;       // bit0  -> qubit 11
            a *= (uk & 2) ? s10 : c10;       // bit1  -> qubit 10
            a *= (uk & 4) ? s9 : c9;         // bit2  -> qubit 9
            a *= ((uk >> 10) & 1) ? s1 : c1; // bit10 -> qubit 1
            a *= ((uk >> 11) & 1) ? s0f : c0;// bit11 -> qubit 0
            v[k] = a;
        }
    }

    // ============ Layers 1..3 ============
#pragma unroll 1
    for (int d = 1; d < DEPTH; ++d) {
        const float* C = CS + d * NQ;
        const float* Sn = SN + d * NQ;

        // ---- Pass A: (d>1: float4 gather; d==1: registers already hold state)
        if (d > 1) {
            const float4 p0 = *reinterpret_cast<const float4*>(&S0[aAddr0]);
            const float4 p1 = *reinterpret_cast<const float4*>(&S0[aAddr1]);
            v[0] = p0.x; v[1] = p0.y; v[2] = p0.z; v[3] = p0.w;
            v[4] = p1.x; v[5] = p1.y; v[6] = p1.z; v[7] = p1.w;
        }
        // rotate qubits 11..9 (k bits, in-reg)
#pragma unroll
        for (int rb = 0; rb < 3; ++rb) {
            const int m = 1 << rb;
            const float c = C[11 - rb], s = Sn[11 - rb];
#pragma unroll
            for (int k = 0; k < 8; ++k)
                if (!(k & m)) {
                    const float lo = v[k], hi = v[k | m];
                    v[k]     = fmaf(c, lo, -s * hi);
                    v[k | m] = fmaf(s, lo,  c * hi);
                }
        }
        // rotate qubits 8..4 (lane shfl)
#pragma unroll
        for (int bs = 0; bs < 5; ++bs) {
            const int m = 1 << bs;
            const float c = C[8 - bs], s = Sn[8 - bs];
            const float se = (lane & m) ? s : -s;
#pragma unroll
            for (int k = 0; k < 8; ++k) {
                const float o = __shfl_xor_sync(0xffffffffu, v[k], m);
                v[k] = fmaf(c, v[k], se * o);
            }
        }
        *reinterpret_cast<float4*>(&S1[aAddr0]) = make_float4(v[0], v[1], v[2], v[3]);
        *reinterpret_cast<float4*>(&S1[aAddr1]) = make_float4(v[4], v[5], v[6], v[7]);
        __syncthreads();

        // ---- Pass B: scalar gather, rotate qubit 3 (shfl lane bit 4) +
        //      qubits 2..0 (k bits). Store S0 with ring fused, except layer 3
        //      which keeps the result in registers for the folded readout.
#pragma unroll
        for (int k = 0; k < 8; ++k) v[k] = S1[bAddr + (k << 9)];

        {
            const float c = C[3], s = Sn[3];
            const float se = (lane & 16) ? s : -s;
#pragma unroll
            for (int k = 0; k < 8; ++k) {
                const float o = __shfl_xor_sync(0xffffffffu, v[k], 16);
                v[k] = fmaf(c, v[k], se * o);
            }
        }
#pragma unroll
        for (int rb = 0; rb < 3; ++rb) {
            const int m = 1 << rb;
            const float c = C[2 - rb], s = Sn[2 - rb];
#pragma unroll
            for (int k = 0; k < 8; ++k)
                if (!(k & m)) {
                    const float lo = v[k], hi = v[k | m];
                    v[k]     = fmaf(c, lo, -s * hi);
                    v[k | m] = fmaf(s, lo,  c * hi);
                }
        }
        if (d < DEPTH - 1) {
#pragma unroll
            for (int k = 0; k < 8; ++k) S0[sb ^ KC2(k)] = v[k];
            __syncthreads();
        }
    }

    // ============ Readout folded into layer-3 pass-B registers ============
    // v[k] = pre-ring value at i = baseB|(k<<9); final state index = sig_inv(i).
    float a0 = 0.f, a1 = 0.f;
#pragma unroll
    for (int k = 0; k < 8; ++k) {
        out[2 + (sOut ^ SI(k))] = v[k];      // scattered but bijective
        const float p = v[k] * v[k];
        a0 = fmaf(p, wa[k], a0);
        a1 = fmaf(p, wb[k], a1);
    }
#pragma unroll
    for (int o = 16; o > 0; o >>= 1) {
        a0 += __shfl_down_sync(0xffffffffu, a0, o);
        a1 += __shfl_down_sync(0xffffffffu, a1, o);
    }
    if (lane == 0) { red[wid] = a0; red[16 + wid] = a1; }
    __syncthreads();
    if (wid == 0) {
        float r0 = (lane < 16) ? red[lane] : 0.f;
        float r1 = (lane < 16) ? red[16 + lane] : 0.f;
#pragma unroll
        for (int o = 8; o > 0; o >>= 1) {
            r0 += __shfl_down_sync(0xffffffffu, r0, o);
            r1 += __shfl_down_sync(0xffffffffu, r1, o);
        }
        if (lane == 0) {
            out[0] = r0 + b[0];
            out[1] = r1 + b[1];
        }
    }
}

extern "C" void kernel_launch(void* const* d_in, const int* in_sizes, int n_in,
                              void* d_out, int out_size) {
    const float* x = nullptr;
    const float* th = nullptr;
    const float* w = nullptr;
    const float* b = nullptr;
    for (int i = 0; i < n_in; ++i) {
        const int s = in_sizes[i];
        if (s == NQ) x = (const float*)d_in[i];
        else if (s == DEPTH * NQ) th = (const float*)d_in[i];
        else if (s == 2 * DIM) w = (const float*)d_in[i];
        else if (s == 2) b = (const float*)d_in[i];
    }
    qsim_kernel<<<1, 512>>>(x, th, w, b, (float*)d_out);
}